// round 12
// baseline (speedup 1.0000x reference)
#include <cuda_runtime.h>
#include <cuda_fp16.h>
#include <cstdint>

// Problem constants
#define NB   2
#define TT   2048
#define DD   1024
#define HH   16
#define HD   64
#define MR   (NB * TT)            // 4096
#define QC   (3 * DD)             // 3072
#define FREQ_C 0.4152410118609203f   // log2(10000)/32

// HMMA GEMM tiling: BK=64, 2-stage, one barrier per stage, 1-pass fp16
#define BK      64
#define GROWB   144                 // 64 fp16 = 128B + 16B pad
#define GTILE   (128 * GROWB)       // 18432 per operand tile
#define GSTG    (2 * GTILE)         // 36864 per stage (A, B)
#define GEMM_SMEM (2 * GSTG)        // 73728

// attention smem (1-pass fp16)
#define KP   144                    // 64 fp16 row + 16B pad
#define VP   272                    // 128 fp16 row + 16B pad
#define SM_K 0
#define SM_V (128 * KP)             // 18432
#define ATTN_SMEM (SM_V + 64 * VP)  // 35840

// ------------------------------ scratch -----------------------------------
__device__ __align__(128) __half g_qkvh[(size_t)MR * QC];
__device__ __align__(128) __half g_xh [(size_t)MR * DD];
__device__ __align__(128) __half g_wqh[(size_t)QC * DD];
__device__ __align__(128) __half g_woh[(size_t)DD * DD];
__device__ __align__(128) __half g_ah [(size_t)MR * DD];
// rope'd attention operands, head-major fp16
__device__ __align__(128) __half g_q [(size_t)NB * HH * TT * HD];
__device__ __align__(128) __half g_k [(size_t)NB * HH * TT * HD];
__device__ __align__(128) __half g_vt[(size_t)NB * HH * HD * TT];

// --------------------------- asm helpers ----------------------------------
__device__ __forceinline__ uint32_t s2u(const void* p) {
    uint32_t a;
    asm("{ .reg .u64 t; cvta.to.shared.u64 t, %1; cvt.u32.u64 %0, t; }"
        : "=r"(a) : "l"(p));
    return a;
}
__device__ __forceinline__ void cp16(uint32_t dst, const void* src) {
    asm volatile("cp.async.cg.shared.global [%0], [%1], 16;"
                 :: "r"(dst), "l"(__cvta_generic_to_global(src)) : "memory");
}
__device__ __forceinline__ void cp_commit() {
    asm volatile("cp.async.commit_group;" ::: "memory");
}
template <int N>
__device__ __forceinline__ void cp_wait() {
    asm volatile("cp.async.wait_group %0;" :: "n"(N) : "memory");
}
__device__ __forceinline__ void ldm_x4(uint32_t& r0, uint32_t& r1,
                                       uint32_t& r2, uint32_t& r3, uint32_t a) {
    asm volatile("ldmatrix.sync.aligned.m8n8.x4.shared.b16 {%0,%1,%2,%3}, [%4];"
                 : "=r"(r0), "=r"(r1), "=r"(r2), "=r"(r3) : "r"(a));
}
__device__ __forceinline__ void mma_f16(float* c, const uint32_t* a,
                                        const uint32_t* b) {
    asm volatile(
        "mma.sync.aligned.m16n8k16.row.col.f32.f16.f16.f32 "
        "{%0,%1,%2,%3}, {%4,%5,%6,%7}, {%8,%9}, {%0,%1,%2,%3};"
        : "+f"(c[0]), "+f"(c[1]), "+f"(c[2]), "+f"(c[3])
        : "r"(a[0]), "r"(a[1]), "r"(a[2]), "r"(a[3]), "r"(b[0]), "r"(b[1]));
}
__device__ __forceinline__ uint32_t packh(float a, float b) {
    __half2 h = __floats2half2_rn(a, b);
    return *reinterpret_cast<uint32_t*>(&h);
}

// ---------------------------------------------------------------------------
// fp32 -> fp16 convert
// ---------------------------------------------------------------------------
__global__ __launch_bounds__(256) void conv_half(
    const float4* __restrict__ src, __half2* __restrict__ dst, int n4)
{
    int i = blockIdx.x * blockDim.x + threadIdx.x;
    if (i >= n4) return;
    float4 v = src[i];
    dst[2 * i]     = __floats2half2_rn(v.x, v.y);
    dst[2 * i + 1] = __floats2half2_rn(v.z, v.w);
}

// ---------------------------------------------------------------------------
// HMMA GEMM, 1-pass fp16: C[M,N] = A[M,K] @ B[N,K]^T (+bias for float out).
// CTA 128x128, 8 warps (2M x 4N), warp tile 64x32, BK=64, 2-stage pipeline.
// ---------------------------------------------------------------------------
template <typename OT>
__global__ __launch_bounds__(256) void gemm_hmma(
    int Ng, int Kg,
    const __half* __restrict__ A, const __half* __restrict__ B,
    const float* __restrict__ bias, OT* __restrict__ C)
{
    extern __shared__ char sm[];
    const uint32_t smb = s2u(sm);

    const int tid  = threadIdx.x;
    const int lane = tid & 31;
    const int wid  = tid >> 5;
    const int wm   = wid & 1;
    const int wn   = wid >> 1;
    const int m0   = blockIdx.y * 128;
    const int n0   = blockIdx.x * 128;

    auto load_stage = [&](int st, int k0) {
        const uint32_t base = smb + st * GSTG;
#pragma unroll
        for (int j = 0; j < 4; j++) {
            const int idx = tid + j * 256;
            const int r = idx >> 3, c = idx & 7;
            const uint32_t d = base + (uint32_t)r * GROWB + c * 16;
            cp16(d,         A + (size_t)(m0 + r) * Kg + k0 + c * 8);
            cp16(d + GTILE, B + (size_t)(n0 + r) * Kg + k0 + c * 8);
        }
    };

    float acc[4][4][4];
#pragma unroll
    for (int i = 0; i < 4; i++)
#pragma unroll
        for (int j = 0; j < 4; j++)
#pragma unroll
            for (int k = 0; k < 4; k++) acc[i][j][k] = 0.f;

    load_stage(0, 0);
    cp_commit();

    const int S = Kg / BK;
    const int lrow = lane & 15, lhalf = lane >> 4;

    for (int s = 0; s < S; s++) {
        cp_wait<0>();
        __syncthreads();
        if (s + 1 < S) { load_stage((s + 1) & 1, (s + 1) * BK); cp_commit(); }

        const uint32_t stb = smb + (s & 1) * GSTG;
        const uint32_t aB = stb + (uint32_t)(wm * 64 + lrow) * GROWB + lhalf * 16;
        const uint32_t bB = stb + GTILE +
                            (uint32_t)(wn * 32 + lrow) * GROWB + lhalf * 16;
#pragma unroll
        for (int kd = 0; kd < 4; kd++) {
            const uint32_t ko = kd * 32;
            uint32_t a[4][4], bh[4][2];
#pragma unroll
            for (int mt = 0; mt < 4; mt++)
                ldm_x4(a[mt][0], a[mt][1], a[mt][2], a[mt][3],
                       aB + ko + mt * 16 * GROWB);
#pragma unroll
            for (int bt = 0; bt < 2; bt++) {
                uint32_t t0, t1, t2, t3;
                ldm_x4(t0, t1, t2, t3, bB + ko + bt * 16 * GROWB);
                bh[bt * 2][0] = t0;  bh[bt * 2][1] = t2;
                bh[bt * 2 + 1][0] = t1;  bh[bt * 2 + 1][1] = t3;
            }
#pragma unroll
            for (int mt = 0; mt < 4; mt++)
#pragma unroll
                for (int nt = 0; nt < 4; nt++)
                    mma_f16(acc[mt][nt], a[mt], bh[nt]);
        }
    }

    const int erow = lane >> 2, ecol = (lane & 3) * 2;
#pragma unroll
    for (int mt = 0; mt < 4; mt++) {
        const int gr = m0 + wm * 64 + mt * 16 + erow;
#pragma unroll
        for (int nt = 0; nt < 4; nt++) {
            const int gc = n0 + wn * 32 + nt * 8 + ecol;
            if constexpr (sizeof(OT) == 4) {
                float b0 = 0.f, b1 = 0.f;
                if (bias) { b0 = bias[gc]; b1 = bias[gc + 1]; }
                float2 v0 = {acc[mt][nt][0] + b0, acc[mt][nt][1] + b1};
                float2 v1 = {acc[mt][nt][2] + b0, acc[mt][nt][3] + b1};
                *(float2*)((float*)C + (size_t)gr * Ng + gc)       = v0;
                *(float2*)((float*)C + (size_t)(gr + 8) * Ng + gc) = v1;
            } else {
                *(uint32_t*)((__half*)C + (size_t)gr * Ng + gc) =
                    packh(acc[mt][nt][0], acc[mt][nt][1]);
                *(uint32_t*)((__half*)C + (size_t)(gr + 8) * Ng + gc) =
                    packh(acc[mt][nt][2], acc[mt][nt][3]);
            }
        }
    }
}

// ---------------------------------------------------------------------------
// prep 1: RoPE + scale(Q) -> head-major fp16 Q/K [nb][h][t][64]
// ---------------------------------------------------------------------------
__global__ __launch_bounds__(256) void rope_conv_qk(
    const __half* __restrict__ qkv,
    __half* __restrict__ Q, __half* __restrict__ K)
{
    const int t0 = blockIdx.x * 64, h = blockIdx.y, nb = blockIdx.z;
    for (int idx = threadIdx.x; idx < 64 * 32; idx += 256) {
        const int tl = idx >> 5, p = idx & 31;
        const int t = t0 + tl;
        const float inv = exp2f(-(float)p * FREQ_C);
        float s, c;
        sincosf((float)t * inv, &s, &c);

        const size_t src = (size_t)(nb * TT + t) * QC + h * HD;
        const size_t dst = ((size_t)(nb * HH + h) * TT + t) * HD;

        const float q1 = __half2float(qkv[src + p]);
        const float q2 = __half2float(qkv[src + p + 32]);
        Q[dst + p]      = __float2half((q1 * c - q2 * s) * 0.125f);
        Q[dst + p + 32] = __float2half((q2 * c + q1 * s) * 0.125f);

        const float k1 = __half2float(qkv[src + DD + p]);
        const float k2 = __half2float(qkv[src + DD + p + 32]);
        K[dst + p]      = __float2half(k1 * c - k2 * s);
        K[dst + p + 32] = __float2half(k2 * c + k1 * s);
    }
}

// ---------------------------------------------------------------------------
// prep 2: V transpose -> Vt [nb][h][d][t] fp16
// ---------------------------------------------------------------------------
__global__ __launch_bounds__(256) void vtrans(
    const __half* __restrict__ qkv, __half* __restrict__ Vt)
{
    __shared__ __half tile[64 * 68];
    const int t0 = blockIdx.x * 64, h = blockIdx.y, nb = blockIdx.z;
    for (int idx = threadIdx.x; idx < 64 * 64; idx += 256) {
        const int tl = idx >> 6, d = idx & 63;
        tile[tl * 68 + d] =
            qkv[(size_t)(nb * TT + t0 + tl) * QC + 2 * DD + h * HD + d];
    }
    __syncthreads();
    for (int idx = threadIdx.x; idx < 64 * 64; idx += 256) {
        const int d = idx >> 6, tl = idx & 63;
        Vt[((size_t)(nb * HH + h) * HD + d) * TT + t0 + tl] = tile[tl * 68 + d];
    }
}

// ---------------------------------------------------------------------------
// MMA flash attention, 1-pass fp16: 128-query tile, 8 warps x 16 rows,
// 3 key chunks of 128 (diagonal first). Writes fp16 attn-out.
// ---------------------------------------------------------------------------
__global__ __launch_bounds__(256, 1) void attn_mma(
    const __half* __restrict__ Q, const __half* __restrict__ K,
    const __half* __restrict__ Vt, __half* __restrict__ oh)
{
    extern __shared__ char sm[];
    const uint32_t smb = s2u(sm);

    const int tid = threadIdx.x, lane = tid & 31, w = tid >> 5;
    const int i0 = blockIdx.x * 128, h = blockIdx.y, nb = blockIdx.z;
    const size_t qkbase = (size_t)(nb * HH + h) * TT;
    const size_t vbase  = (size_t)(nb * HH + h) * HD;

    const int lrow = lane & 15, half = lane >> 4;
    const int g = lane >> 2, qc = lane & 3;
    const int rl0 = w * 16 + g, rl1 = rl0 + 8;

    // stage Q tile into SM_K area, pull frags to registers
    for (int idx = tid; idx < 128 * 8; idx += 256) {
        const int r = idx >> 3, c = idx & 7;
        cp16(smb + SM_K + r * KP + c * 16,
             Q + (qkbase + i0 + r) * HD + c * 8);
    }
    cp_commit(); cp_wait<0>(); __syncthreads();

    uint32_t qf[4][4];
    {
        const uint32_t aB = smb + SM_K + (uint32_t)(w * 16 + lrow) * KP + half * 16;
#pragma unroll
        for (int kd = 0; kd < 4; kd++)
            ldm_x4(qf[kd][0], qf[kd][1], qf[kd][2], qf[kd][3], aB + kd * 32);
    }
    __syncthreads();

    float of[8][4];
#pragma unroll
    for (int i = 0; i < 8; i++)
#pragma unroll
        for (int j = 0; j < 4; j++) of[i][j] = 0.f;
    float m0 = -1e30f, m1 = -1e30f, l0 = 0.f, l1 = 0.f;

#pragma unroll
    for (int cc = 0; cc < 3; cc++) {
        const int cm = (cc == 0) ? 1 : (cc == 1) ? 0 : 2;   // diag, left, right
        const int j0 = i0 + (cm - 1) * 128;
        if (j0 < 0 || j0 >= TT) continue;

        // load K chunk (128x64) + V chunk (64x128, d-major)
        for (int idx = tid; idx < 128 * 8; idx += 256) {
            const int r = idx >> 3, c = idx & 7;
            cp16(smb + SM_K + r * KP + c * 16,
                 K + (qkbase + j0 + r) * HD + c * 8);
        }
        for (int idx = tid; idx < 64 * 16; idx += 256) {
            const int r = idx >> 4, c = idx & 15;
            cp16(smb + SM_V + r * VP + c * 16,
                 Vt + (vbase + r) * TT + j0 + c * 8);
        }
        cp_commit(); cp_wait<0>(); __syncthreads();

        // S = Q K^T (1-pass fp16)
        float sf[16][4];
#pragma unroll
        for (int i = 0; i < 16; i++)
#pragma unroll
            for (int j = 0; j < 4; j++) sf[i][j] = 0.f;

        const uint32_t bB = smb + SM_K + (uint32_t)lrow * KP + half * 16;
#pragma unroll
        for (int kd = 0; kd < 4; kd++) {
#pragma unroll
            for (int nt16 = 0; nt16 < 8; nt16++) {
                uint32_t t0, t1, t2, t3;
                ldm_x4(t0, t1, t2, t3, bB + nt16 * 16 * KP + kd * 32);
                uint32_t b0[2] = {t0, t2}, b1[2] = {t1, t3};
                mma_f16(sf[2 * nt16],     qf[kd], b0);
                mma_f16(sf[2 * nt16 + 1], qf[kd], b1);
            }
        }

        // band mask
        if (cm == 0) {            // left chunk: need col >= rl+1
#pragma unroll
            for (int nt = 0; nt < 16; nt++) {
                const int col = nt * 8 + 2 * qc;
                if (col     <= rl0) sf[nt][0] = -1e30f;
                if (col + 1 <= rl0) sf[nt][1] = -1e30f;
                if (col     <= rl1) sf[nt][2] = -1e30f;
                if (col + 1 <= rl1) sf[nt][3] = -1e30f;
            }
        } else if (cm == 2) {     // right chunk: need col <= rl
#pragma unroll
            for (int nt = 0; nt < 16; nt++) {
                const int col = nt * 8 + 2 * qc;
                if (col     > rl0) sf[nt][0] = -1e30f;
                if (col + 1 > rl0) sf[nt][1] = -1e30f;
                if (col     > rl1) sf[nt][2] = -1e30f;
                if (col + 1 > rl1) sf[nt][3] = -1e30f;
            }
        }

        // online softmax
        float mx0 = -1e30f, mx1 = -1e30f;
#pragma unroll
        for (int nt = 0; nt < 16; nt++) {
            mx0 = fmaxf(mx0, fmaxf(sf[nt][0], sf[nt][1]));
            mx1 = fmaxf(mx1, fmaxf(sf[nt][2], sf[nt][3]));
        }
        mx0 = fmaxf(mx0, __shfl_xor_sync(0xffffffffu, mx0, 1));
        mx0 = fmaxf(mx0, __shfl_xor_sync(0xffffffffu, mx0, 2));
        mx1 = fmaxf(mx1, __shfl_xor_sync(0xffffffffu, mx1, 1));
        mx1 = fmaxf(mx1, __shfl_xor_sync(0xffffffffu, mx1, 2));
        const float mn0 = fmaxf(m0, mx0), mn1 = fmaxf(m1, mx1);
        const float a0 = __expf(m0 - mn0), a1 = __expf(m1 - mn1);
        m0 = mn0; m1 = mn1;
        float s0 = 0.f, s1 = 0.f;
#pragma unroll
        for (int nt = 0; nt < 16; nt++) {
            sf[nt][0] = __expf(sf[nt][0] - m0);
            sf[nt][1] = __expf(sf[nt][1] - m0);
            sf[nt][2] = __expf(sf[nt][2] - m1);
            sf[nt][3] = __expf(sf[nt][3] - m1);
            s0 += sf[nt][0] + sf[nt][1];
            s1 += sf[nt][2] + sf[nt][3];
        }
        s0 += __shfl_xor_sync(0xffffffffu, s0, 1);
        s0 += __shfl_xor_sync(0xffffffffu, s0, 2);
        s1 += __shfl_xor_sync(0xffffffffu, s1, 1);
        s1 += __shfl_xor_sync(0xffffffffu, s1, 2);
        l0 = l0 * a0 + s0;
        l1 = l1 * a1 + s1;
#pragma unroll
        for (int nt = 0; nt < 8; nt++) {
            of[nt][0] *= a0; of[nt][1] *= a0;
            of[nt][2] *= a1; of[nt][3] *= a1;
        }

        // O += P V (1-pass fp16)
        const uint32_t vB = smb + SM_V + (uint32_t)lrow * VP + half * 16;
#pragma unroll
        for (int kk = 0; kk < 8; kk++) {
            uint32_t ph[4];
            ph[0] = packh(sf[2 * kk][0],     sf[2 * kk][1]);
            ph[1] = packh(sf[2 * kk][2],     sf[2 * kk][3]);
            ph[2] = packh(sf[2 * kk + 1][0], sf[2 * kk + 1][1]);
            ph[3] = packh(sf[2 * kk + 1][2], sf[2 * kk + 1][3]);
#pragma unroll
            for (int nv = 0; nv < 4; nv++) {
                uint32_t t0, t1, t2, t3;
                ldm_x4(t0, t1, t2, t3, vB + nv * 16 * VP + kk * 32);
                uint32_t v0[2] = {t0, t2}, v1[2] = {t1, t3};
                mma_f16(of[2 * nv],     ph, v0);
                mma_f16(of[2 * nv + 1], ph, v1);
            }
        }
        __syncthreads();
    }

    // normalize, convert to fp16, store
    const float i0f = 1.0f / l0, i1f = 1.0f / l1;
    const int tg0 = i0 + rl0, tg1 = i0 + rl1;
#pragma unroll
    for (int nt = 0; nt < 8; nt++) {
        const int col = h * HD + nt * 8 + 2 * qc;
        *(uint32_t*)(oh + (size_t)(nb * TT + tg0) * DD + col) =
            packh(of[nt][0] * i0f, of[nt][1] * i0f);
        *(uint32_t*)(oh + (size_t)(nb * TT + tg1) * DD + col) =
            packh(of[nt][2] * i1f, of[nt][3] * i1f);
    }
}

// ---------------------------------------------------------------------------
extern "C" void kernel_launch(void* const* d_in, const int* in_sizes, int n_in,
                              void* d_out, int out_size)
{
    const float* x     = (const float*)d_in[0];
    const float* w_qkv = (const float*)d_in[1];
    const float* w_out = (const float*)d_in[2];
    const float* b_out = (const float*)d_in[3];
    float* out = (float*)d_out;

    __half *qkvh, *xh, *wqh, *woh, *ah, *q, *k, *vt;
    cudaGetSymbolAddress((void**)&qkvh, g_qkvh);
    cudaGetSymbolAddress((void**)&xh,  g_xh);
    cudaGetSymbolAddress((void**)&wqh, g_wqh);
    cudaGetSymbolAddress((void**)&woh, g_woh);
    cudaGetSymbolAddress((void**)&ah,  g_ah);
    cudaGetSymbolAddress((void**)&q,   g_q);
    cudaGetSymbolAddress((void**)&k,   g_k);
    cudaGetSymbolAddress((void**)&vt,  g_vt);

    cudaFuncSetAttribute(gemm_hmma<__half>,
                         cudaFuncAttributeMaxDynamicSharedMemorySize, GEMM_SMEM);
    cudaFuncSetAttribute(gemm_hmma<float>,
                         cudaFuncAttributeMaxDynamicSharedMemorySize, GEMM_SMEM);
    cudaFuncSetAttribute(attn_mma,
                         cudaFuncAttributeMaxDynamicSharedMemorySize, ATTN_SMEM);

    // 1) convert x, w_qkv, w_out to fp16
    {
        int n4 = MR * DD / 4;
        conv_half<<<(n4 + 255) / 256, 256>>>((const float4*)x, (__half2*)xh, n4);
        n4 = QC * DD / 4;
        conv_half<<<(n4 + 255) / 256, 256>>>(
            (const float4*)w_qkv, (__half2*)wqh, n4);
        n4 = DD * DD / 4;
        conv_half<<<(n4 + 255) / 256, 256>>>(
            (const float4*)w_out, (__half2*)woh, n4);
    }

    // 2) QKV projection (fp16 HMMA, fp16 output)
    {
        dim3 grid(QC / 128, MR / 128);
        gemm_hmma<__half><<<grid, 256, GEMM_SMEM>>>(QC, DD, xh, wqh,
                                                    nullptr, qkvh);
    }

    // 3) prep: RoPE Q/K (fp16), transpose V (fp16)
    {
        dim3 grid(TT / 64, HH, NB);
        rope_conv_qk<<<grid, 256>>>(qkvh, q, k);
        vtrans<<<grid, 256>>>(qkvh, vt);
    }

    // 4) MMA flash attention (banded, 1-pass fp16) -> ah fp16
    {
        dim3 grid(TT / 128, HH, NB);
        attn_mma<<<grid, 256, ATTN_SMEM>>>(q, k, vt, ah);
    }

    // 5) output projection (fp16 HMMA) + bias -> fp32 out
    {
        dim3 grid(DD / 128, MR / 128);
        gemm_hmma<float><<<grid, 256, GEMM_SMEM>>>(DD, DD, ah, woh, b_out, out);
    }
}

// round 13
// speedup vs baseline: 1.5253x; 1.5253x over previous
#include <cuda_runtime.h>
#include <cuda_fp16.h>
#include <cstdint>

// Problem constants
#define NB   2
#define TT   2048
#define DD   1024
#define HH   16
#define HD   64
#define MR   (NB * TT)            // 4096
#define QC   (3 * DD)             // 3072
#define FREQ_C 0.4152410118609203f   // log2(10000)/32

// HMMA GEMM tiling: BK=64, 2-stage, one barrier per stage, 1-pass fp16
#define BK      64
#define GROWB   144                 // 64 fp16 = 128B + 16B pad
#define GTILE   (128 * GROWB)       // 18432 per operand tile
#define GSTG    (2 * GTILE)         // 36864 per stage (A, B)
#define GEMM_SMEM (2 * GSTG)        // 73728

// attention smem (1-pass fp16)
#define KP   144                    // 64 fp16 row + 16B pad
#define VP   272                    // 128 fp16 row + 16B pad
#define SM_K 0
#define SM_V (128 * KP)             // 18432
#define ATTN_SMEM (SM_V + 64 * VP)  // 35840

// ------------------------------ scratch -----------------------------------
__device__ __align__(128) __half g_qkvh[(size_t)MR * QC];
__device__ __align__(128) __half g_xh [(size_t)MR * DD];
__device__ __align__(128) __half g_wqh[(size_t)QC * DD];
__device__ __align__(128) __half g_woh[(size_t)DD * DD];
__device__ __align__(128) __half g_ah [(size_t)MR * DD];
// rope'd attention operands, head-major fp16
__device__ __align__(128) __half g_q [(size_t)NB * HH * TT * HD];
__device__ __align__(128) __half g_k [(size_t)NB * HH * TT * HD];
__device__ __align__(128) __half g_vt[(size_t)NB * HH * HD * TT];

// --------------------------- asm helpers ----------------------------------
__device__ __forceinline__ uint32_t s2u(const void* p) {
    uint32_t a;
    asm("{ .reg .u64 t; cvta.to.shared.u64 t, %1; cvt.u32.u64 %0, t; }"
        : "=r"(a) : "l"(p));
    return a;
}
__device__ __forceinline__ void cp16(uint32_t dst, const void* src) {
    asm volatile("cp.async.cg.shared.global [%0], [%1], 16;"
                 :: "r"(dst), "l"(__cvta_generic_to_global(src)) : "memory");
}
__device__ __forceinline__ void cp_commit() {
    asm volatile("cp.async.commit_group;" ::: "memory");
}
template <int N>
__device__ __forceinline__ void cp_wait() {
    asm volatile("cp.async.wait_group %0;" :: "n"(N) : "memory");
}
__device__ __forceinline__ void ldm_x4(uint32_t& r0, uint32_t& r1,
                                       uint32_t& r2, uint32_t& r3, uint32_t a) {
    asm volatile("ldmatrix.sync.aligned.m8n8.x4.shared.b16 {%0,%1,%2,%3}, [%4];"
                 : "=r"(r0), "=r"(r1), "=r"(r2), "=r"(r3) : "r"(a));
}
__device__ __forceinline__ void mma_f16(float* c, const uint32_t* a,
                                        const uint32_t* b) {
    asm volatile(
        "mma.sync.aligned.m16n8k16.row.col.f32.f16.f16.f32 "
        "{%0,%1,%2,%3}, {%4,%5,%6,%7}, {%8,%9}, {%0,%1,%2,%3};"
        : "+f"(c[0]), "+f"(c[1]), "+f"(c[2]), "+f"(c[3])
        : "r"(a[0]), "r"(a[1]), "r"(a[2]), "r"(a[3]), "r"(b[0]), "r"(b[1]));
}
__device__ __forceinline__ uint32_t packh(float a, float b) {
    __half2 h = __floats2half2_rn(a, b);
    return *reinterpret_cast<uint32_t*>(&h);
}

// ---------------------------------------------------------------------------
// fused fp32 -> fp16 convert of x, w_qkv, w_out (one launch)
// ---------------------------------------------------------------------------
#define N4_X  (MR * DD / 4)
#define N4_WQ (QC * DD / 4)
#define N4_WO (DD * DD / 4)
__global__ __launch_bounds__(256) void conv_all(
    const float4* __restrict__ x, const float4* __restrict__ wq,
    const float4* __restrict__ wo,
    __half2* __restrict__ xh, __half2* __restrict__ wqh,
    __half2* __restrict__ woh)
{
    int i = blockIdx.x * blockDim.x + threadIdx.x;
    const float4* src;
    __half2* dst;
    if (i < N4_X)                { src = x;  dst = xh;  }
    else if (i < N4_X + N4_WQ)   { i -= N4_X;  src = wq; dst = wqh; }
    else if (i < N4_X + N4_WQ + N4_WO) { i -= N4_X + N4_WQ; src = wo; dst = woh; }
    else return;
    float4 v = src[i];
    dst[2 * i]     = __floats2half2_rn(v.x, v.y);
    dst[2 * i + 1] = __floats2half2_rn(v.z, v.w);
}

// ---------------------------------------------------------------------------
// HMMA GEMM, 1-pass fp16: C[M,N] = A[M,K] @ B[N,K]^T (+bias for float out).
// CTA 128x128, 8 warps (2M x 4N), warp tile 64x32, BK=64, 2-stage pipeline.
// ---------------------------------------------------------------------------
template <typename OT>
__global__ __launch_bounds__(256) void gemm_hmma(
    int Ng, int Kg,
    const __half* __restrict__ A, const __half* __restrict__ B,
    const float* __restrict__ bias, OT* __restrict__ C)
{
    extern __shared__ char sm[];
    const uint32_t smb = s2u(sm);

    const int tid  = threadIdx.x;
    const int lane = tid & 31;
    const int wid  = tid >> 5;
    const int wm   = wid & 1;
    const int wn   = wid >> 1;
    const int m0   = blockIdx.y * 128;
    const int n0   = blockIdx.x * 128;

    auto load_stage = [&](int st, int k0) {
        const uint32_t base = smb + st * GSTG;
#pragma unroll
        for (int j = 0; j < 4; j++) {
            const int idx = tid + j * 256;
            const int r = idx >> 3, c = idx & 7;
            const uint32_t d = base + (uint32_t)r * GROWB + c * 16;
            cp16(d,         A + (size_t)(m0 + r) * Kg + k0 + c * 8);
            cp16(d + GTILE, B + (size_t)(n0 + r) * Kg + k0 + c * 8);
        }
    };

    float acc[4][4][4];
#pragma unroll
    for (int i = 0; i < 4; i++)
#pragma unroll
        for (int j = 0; j < 4; j++)
#pragma unroll
            for (int k = 0; k < 4; k++) acc[i][j][k] = 0.f;

    load_stage(0, 0);
    cp_commit();

    const int S = Kg / BK;
    const int lrow = lane & 15, lhalf = lane >> 4;

    for (int s = 0; s < S; s++) {
        cp_wait<0>();
        __syncthreads();
        if (s + 1 < S) { load_stage((s + 1) & 1, (s + 1) * BK); cp_commit(); }

        const uint32_t stb = smb + (s & 1) * GSTG;
        const uint32_t aB = stb + (uint32_t)(wm * 64 + lrow) * GROWB + lhalf * 16;
        const uint32_t bB = stb + GTILE +
                            (uint32_t)(wn * 32 + lrow) * GROWB + lhalf * 16;
#pragma unroll
        for (int kd = 0; kd < 4; kd++) {
            const uint32_t ko = kd * 32;
            uint32_t a[4][4], bh[4][2];
#pragma unroll
            for (int mt = 0; mt < 4; mt++)
                ldm_x4(a[mt][0], a[mt][1], a[mt][2], a[mt][3],
                       aB + ko + mt * 16 * GROWB);
#pragma unroll
            for (int bt = 0; bt < 2; bt++) {
                uint32_t t0, t1, t2, t3;
                ldm_x4(t0, t1, t2, t3, bB + ko + bt * 16 * GROWB);
                bh[bt * 2][0] = t0;  bh[bt * 2][1] = t2;
                bh[bt * 2 + 1][0] = t1;  bh[bt * 2 + 1][1] = t3;
            }
#pragma unroll
            for (int mt = 0; mt < 4; mt++)
#pragma unroll
                for (int nt = 0; nt < 4; nt++)
                    mma_f16(acc[mt][nt], a[mt], bh[nt]);
        }
    }

    const int erow = lane >> 2, ecol = (lane & 3) * 2;
#pragma unroll
    for (int mt = 0; mt < 4; mt++) {
        const int gr = m0 + wm * 64 + mt * 16 + erow;
#pragma unroll
        for (int nt = 0; nt < 4; nt++) {
            const int gc = n0 + wn * 32 + nt * 8 + ecol;
            if constexpr (sizeof(OT) == 4) {
                float b0 = 0.f, b1 = 0.f;
                if (bias) { b0 = bias[gc]; b1 = bias[gc + 1]; }
                float2 v0 = {acc[mt][nt][0] + b0, acc[mt][nt][1] + b1};
                float2 v1 = {acc[mt][nt][2] + b0, acc[mt][nt][3] + b1};
                *(float2*)((float*)C + (size_t)gr * Ng + gc)       = v0;
                *(float2*)((float*)C + (size_t)(gr + 8) * Ng + gc) = v1;
            } else {
                *(uint32_t*)((__half*)C + (size_t)gr * Ng + gc) =
                    packh(acc[mt][nt][0], acc[mt][nt][1]);
                *(uint32_t*)((__half*)C + (size_t)(gr + 8) * Ng + gc) =
                    packh(acc[mt][nt][2], acc[mt][nt][3]);
            }
        }
    }
}

// ---------------------------------------------------------------------------
// fused prep: RoPE+scale Q/K -> head-major [nb][h][t][64]  AND
//             V transpose -> Vt [nb][h][d][t]   (one kernel, one qkv sweep)
// ---------------------------------------------------------------------------
__global__ __launch_bounds__(256) void prep_qkv(
    const __half* __restrict__ qkv,
    __half* __restrict__ Q, __half* __restrict__ K, __half* __restrict__ Vt)
{
    __shared__ __half tile[64 * 68];
    const int t0 = blockIdx.x * 64, h = blockIdx.y, nb = blockIdx.z;

    // V rows -> shared (row-major), then transposed store
    for (int idx = threadIdx.x; idx < 64 * 64; idx += 256) {
        const int tl = idx >> 6, d = idx & 63;
        tile[tl * 68 + d] =
            qkv[(size_t)(nb * TT + t0 + tl) * QC + 2 * DD + h * HD + d];
    }

    // RoPE Q/K (independent of the shared tile)
    for (int idx = threadIdx.x; idx < 64 * 32; idx += 256) {
        const int tl = idx >> 5, p = idx & 31;
        const int t = t0 + tl;
        const float inv = exp2f(-(float)p * FREQ_C);
        float s, c;
        sincosf((float)t * inv, &s, &c);

        const size_t src = (size_t)(nb * TT + t) * QC + h * HD;
        const size_t dst = ((size_t)(nb * HH + h) * TT + t) * HD;

        const float q1 = __half2float(qkv[src + p]);
        const float q2 = __half2float(qkv[src + p + 32]);
        Q[dst + p]      = __float2half((q1 * c - q2 * s) * 0.125f);
        Q[dst + p + 32] = __float2half((q2 * c + q1 * s) * 0.125f);

        const float k1 = __half2float(qkv[src + DD + p]);
        const float k2 = __half2float(qkv[src + DD + p + 32]);
        K[dst + p]      = __float2half(k1 * c - k2 * s);
        K[dst + p + 32] = __float2half(k2 * c + k1 * s);
    }
    __syncthreads();
    for (int idx = threadIdx.x; idx < 64 * 64; idx += 256) {
        const int d = idx >> 6, tl = idx & 63;
        Vt[((size_t)(nb * HH + h) * HD + d) * TT + t0 + tl] = tile[tl * 68 + d];
    }
}

// ---------------------------------------------------------------------------
// MMA flash attention, 1-pass fp16: 128-query tile, 8 warps x 16 rows,
// 3 key chunks of 128 (diagonal first). Writes fp16 attn-out.
// ---------------------------------------------------------------------------
__global__ __launch_bounds__(256, 1) void attn_mma(
    const __half* __restrict__ Q, const __half* __restrict__ K,
    const __half* __restrict__ Vt, __half* __restrict__ oh)
{
    extern __shared__ char sm[];
    const uint32_t smb = s2u(sm);

    const int tid = threadIdx.x, lane = tid & 31, w = tid >> 5;
    const int i0 = blockIdx.x * 128, h = blockIdx.y, nb = blockIdx.z;
    const size_t qkbase = (size_t)(nb * HH + h) * TT;
    const size_t vbase  = (size_t)(nb * HH + h) * HD;

    const int lrow = lane & 15, half = lane >> 4;
    const int g = lane >> 2, qc = lane & 3;
    const int rl0 = w * 16 + g, rl1 = rl0 + 8;

    // stage Q tile into SM_K area, pull frags to registers
    for (int idx = tid; idx < 128 * 8; idx += 256) {
        const int r = idx >> 3, c = idx & 7;
        cp16(smb + SM_K + r * KP + c * 16,
             Q + (qkbase + i0 + r) * HD + c * 8);
    }
    cp_commit(); cp_wait<0>(); __syncthreads();

    uint32_t qf[4][4];
    {
        const uint32_t aB = smb + SM_K + (uint32_t)(w * 16 + lrow) * KP + half * 16;
#pragma unroll
        for (int kd = 0; kd < 4; kd++)
            ldm_x4(qf[kd][0], qf[kd][1], qf[kd][2], qf[kd][3], aB + kd * 32);
    }
    __syncthreads();

    float of[8][4];
#pragma unroll
    for (int i = 0; i < 8; i++)
#pragma unroll
        for (int j = 0; j < 4; j++) of[i][j] = 0.f;
    float m0 = -1e30f, m1 = -1e30f, l0 = 0.f, l1 = 0.f;

#pragma unroll
    for (int cc = 0; cc < 3; cc++) {
        const int cm = (cc == 0) ? 1 : (cc == 1) ? 0 : 2;   // diag, left, right
        const int j0 = i0 + (cm - 1) * 128;
        if (j0 < 0 || j0 >= TT) continue;

        // load K chunk (128x64) + V chunk (64x128, d-major)
        for (int idx = tid; idx < 128 * 8; idx += 256) {
            const int r = idx >> 3, c = idx & 7;
            cp16(smb + SM_K + r * KP + c * 16,
                 K + (qkbase + j0 + r) * HD + c * 8);
        }
        for (int idx = tid; idx < 64 * 16; idx += 256) {
            const int r = idx >> 4, c = idx & 15;
            cp16(smb + SM_V + r * VP + c * 16,
                 Vt + (vbase + r) * TT + j0 + c * 8);
        }
        cp_commit(); cp_wait<0>(); __syncthreads();

        // S = Q K^T (1-pass fp16)
        float sf[16][4];
#pragma unroll
        for (int i = 0; i < 16; i++)
#pragma unroll
            for (int j = 0; j < 4; j++) sf[i][j] = 0.f;

        const uint32_t bB = smb + SM_K + (uint32_t)lrow * KP + half * 16;
#pragma unroll
        for (int kd = 0; kd < 4; kd++) {
#pragma unroll
            for (int nt16 = 0; nt16 < 8; nt16++) {
                uint32_t t0, t1, t2, t3;
                ldm_x4(t0, t1, t2, t3, bB + nt16 * 16 * KP + kd * 32);
                uint32_t b0[2] = {t0, t2}, b1[2] = {t1, t3};
                mma_f16(sf[2 * nt16],     qf[kd], b0);
                mma_f16(sf[2 * nt16 + 1], qf[kd], b1);
            }
        }

        // band mask
        if (cm == 0) {            // left chunk: need col >= rl+1
#pragma unroll
            for (int nt = 0; nt < 16; nt++) {
                const int col = nt * 8 + 2 * qc;
                if (col     <= rl0) sf[nt][0] = -1e30f;
                if (col + 1 <= rl0) sf[nt][1] = -1e30f;
                if (col     <= rl1) sf[nt][2] = -1e30f;
                if (col + 1 <= rl1) sf[nt][3] = -1e30f;
            }
        } else if (cm == 2) {     // right chunk: need col <= rl
#pragma unroll
            for (int nt = 0; nt < 16; nt++) {
                const int col = nt * 8 + 2 * qc;
                if (col     > rl0) sf[nt][0] = -1e30f;
                if (col + 1 > rl0) sf[nt][1] = -1e30f;
                if (col     > rl1) sf[nt][2] = -1e30f;
                if (col + 1 > rl1) sf[nt][3] = -1e30f;
            }
        }

        // online softmax
        float mx0 = -1e30f, mx1 = -1e30f;
#pragma unroll
        for (int nt = 0; nt < 16; nt++) {
            mx0 = fmaxf(mx0, fmaxf(sf[nt][0], sf[nt][1]));
            mx1 = fmaxf(mx1, fmaxf(sf[nt][2], sf[nt][3]));
        }
        mx0 = fmaxf(mx0, __shfl_xor_sync(0xffffffffu, mx0, 1));
        mx0 = fmaxf(mx0, __shfl_xor_sync(0xffffffffu, mx0, 2));
        mx1 = fmaxf(mx1, __shfl_xor_sync(0xffffffffu, mx1, 1));
        mx1 = fmaxf(mx1, __shfl_xor_sync(0xffffffffu, mx1, 2));
        const float mn0 = fmaxf(m0, mx0), mn1 = fmaxf(m1, mx1);
        const float a0 = __expf(m0 - mn0), a1 = __expf(m1 - mn1);
        m0 = mn0; m1 = mn1;
        float s0 = 0.f, s1 = 0.f;
#pragma unroll
        for (int nt = 0; nt < 16; nt++) {
            sf[nt][0] = __expf(sf[nt][0] - m0);
            sf[nt][1] = __expf(sf[nt][1] - m0);
            sf[nt][2] = __expf(sf[nt][2] - m1);
            sf[nt][3] = __expf(sf[nt][3] - m1);
            s0 += sf[nt][0] + sf[nt][1];
            s1 += sf[nt][2] + sf[nt][3];
        }
        s0 += __shfl_xor_sync(0xffffffffu, s0, 1);
        s0 += __shfl_xor_sync(0xffffffffu, s0, 2);
        s1 += __shfl_xor_sync(0xffffffffu, s1, 1);
        s1 += __shfl_xor_sync(0xffffffffu, s1, 2);
        l0 = l0 * a0 + s0;
        l1 = l1 * a1 + s1;
#pragma unroll
        for (int nt = 0; nt < 8; nt++) {
            of[nt][0] *= a0; of[nt][1] *= a0;
            of[nt][2] *= a1; of[nt][3] *= a1;
        }

        // O += P V (1-pass fp16)
        const uint32_t vB = smb + SM_V + (uint32_t)lrow * VP + half * 16;
#pragma unroll
        for (int kk = 0; kk < 8; kk++) {
            uint32_t ph[4];
            ph[0] = packh(sf[2 * kk][0],     sf[2 * kk][1]);
            ph[1] = packh(sf[2 * kk][2],     sf[2 * kk][3]);
            ph[2] = packh(sf[2 * kk + 1][0], sf[2 * kk + 1][1]);
            ph[3] = packh(sf[2 * kk + 1][2], sf[2 * kk + 1][3]);
#pragma unroll
            for (int nv = 0; nv < 4; nv++) {
                uint32_t t0, t1, t2, t3;
                ldm_x4(t0, t1, t2, t3, vB + nv * 16 * VP + kk * 32);
                uint32_t v0[2] = {t0, t2}, v1[2] = {t1, t3};
                mma_f16(of[2 * nv],     ph, v0);
                mma_f16(of[2 * nv + 1], ph, v1);
            }
        }
        __syncthreads();
    }

    // normalize, convert to fp16, store
    const float i0f = 1.0f / l0, i1f = 1.0f / l1;
    const int tg0 = i0 + rl0, tg1 = i0 + rl1;
#pragma unroll
    for (int nt = 0; nt < 8; nt++) {
        const int col = h * HD + nt * 8 + 2 * qc;
        *(uint32_t*)(oh + (size_t)(nb * TT + tg0) * DD + col) =
            packh(of[nt][0] * i0f, of[nt][1] * i0f);
        *(uint32_t*)(oh + (size_t)(nb * TT + tg1) * DD + col) =
            packh(of[nt][2] * i1f, of[nt][3] * i1f);
    }
}

// ---------------------------------------------------------------------------
extern "C" void kernel_launch(void* const* d_in, const int* in_sizes, int n_in,
                              void* d_out, int out_size)
{
    const float* x     = (const float*)d_in[0];
    const float* w_qkv = (const float*)d_in[1];
    const float* w_out = (const float*)d_in[2];
    const float* b_out = (const float*)d_in[3];
    float* out = (float*)d_out;

    __half *qkvh, *xh, *wqh, *woh, *ah, *q, *k, *vt;
    cudaGetSymbolAddress((void**)&qkvh, g_qkvh);
    cudaGetSymbolAddress((void**)&xh,  g_xh);
    cudaGetSymbolAddress((void**)&wqh, g_wqh);
    cudaGetSymbolAddress((void**)&woh, g_woh);
    cudaGetSymbolAddress((void**)&ah,  g_ah);
    cudaGetSymbolAddress((void**)&q,   g_q);
    cudaGetSymbolAddress((void**)&k,   g_k);
    cudaGetSymbolAddress((void**)&vt,  g_vt);

    cudaFuncSetAttribute(gemm_hmma<__half>,
                         cudaFuncAttributeMaxDynamicSharedMemorySize, GEMM_SMEM);
    cudaFuncSetAttribute(gemm_hmma<float>,
                         cudaFuncAttributeMaxDynamicSharedMemorySize, GEMM_SMEM);
    cudaFuncSetAttribute(attn_mma,
                         cudaFuncAttributeMaxDynamicSharedMemorySize, ATTN_SMEM);

    // 1) convert x, w_qkv, w_out to fp16 (single fused launch)
    {
        const int n4 = N4_X + N4_WQ + N4_WO;
        conv_all<<<(n4 + 255) / 256, 256>>>(
            (const float4*)x, (const float4*)w_qkv, (const float4*)w_out,
            (__half2*)xh, (__half2*)wqh, (__half2*)woh);
    }

    // 2) QKV projection (fp16 HMMA, fp16 output)
    {
        dim3 grid(QC / 128, MR / 128);
        gemm_hmma<__half><<<grid, 256, GEMM_SMEM>>>(QC, DD, xh, wqh,
                                                    nullptr, qkvh);
    }

    // 3) fused prep: RoPE Q/K + V transpose (fp16)
    {
        dim3 grid(TT / 64, HH, NB);
        prep_qkv<<<grid, 256>>>(qkvh, q, k, vt);
    }

    // 4) MMA flash attention (banded, 1-pass fp16) -> ah fp16
    {
        dim3 grid(TT / 128, HH, NB);
        attn_mma<<<grid, 256, ATTN_SMEM>>>(q, k, vt, ah);
    }

    // 5) output projection (fp16 HMMA) + bias -> fp32 out
    {
        dim3 grid(DD / 128, MR / 128);
        gemm_hmma<float><<<grid, 256, GEMM_SMEM>>>(DD, DD, ah, woh, b_out, out);
    }
}

// round 16
// speedup vs baseline: 1.7014x; 1.1154x over previous
#include <cuda_runtime.h>
#include <cuda_fp16.h>
#include <cstdint>

// Problem constants
#define NB   2
#define TT   2048
#define DD   1024
#define HH   16
#define HD   64
#define MR   (NB * TT)            // 4096
#define QC   (3 * DD)             // 3072
#define FREQ_C 0.4152410118609203f   // log2(10000)/32

// HMMA GEMM tiling: BK=64, 2-stage, one barrier per stage, 1-pass fp16
#define BK      64
#define GROWB   144                 // 64 fp16 = 128B + 16B pad
#define GTILE   (128 * GROWB)       // 18432 per operand tile
#define GSTG    (2 * GTILE)         // 36864 per stage (A, B)
#define GEMM_SMEM (2 * GSTG)        // 73728

// epilogue staging pitch (fp16 elems): 130 -> 260B rows, conflict-free cols
#define SP_E 130

// attention smem (1-pass fp16)
#define KP   144                    // 64 fp16 row + 16B pad
#define VP   272                    // 128 fp16 row + 16B pad
#define SM_K 0
#define SM_V (128 * KP)             // 18432
#define ATTN_SMEM (SM_V + 64 * VP)  // 35840

// ------------------------------ scratch -----------------------------------
__device__ __align__(128) __half g_xh [(size_t)MR * DD];
__device__ __align__(128) __half g_wqh[(size_t)QC * DD];
__device__ __align__(128) __half g_woh[(size_t)DD * DD];
__device__ __align__(128) __half g_ah [(size_t)MR * DD];
// rope'd attention operands, head-major fp16
__device__ __align__(128) __half g_q [(size_t)NB * HH * TT * HD];
__device__ __align__(128) __half g_k [(size_t)NB * HH * TT * HD];
__device__ __align__(128) __half g_vt[(size_t)NB * HH * HD * TT];

// --------------------------- asm helpers ----------------------------------
__device__ __forceinline__ uint32_t s2u(const void* p) {
    uint32_t a;
    asm("{ .reg .u64 t; cvta.to.shared.u64 t, %1; cvt.u32.u64 %0, t; }"
        : "=r"(a) : "l"(p));
    return a;
}
__device__ __forceinline__ void cp16(uint32_t dst, const void* src) {
    asm volatile("cp.async.cg.shared.global [%0], [%1], 16;"
                 :: "r"(dst), "l"(__cvta_generic_to_global(src)) : "memory");
}
__device__ __forceinline__ void cp_commit() {
    asm volatile("cp.async.commit_group;" ::: "memory");
}
template <int N>
__device__ __forceinline__ void cp_wait() {
    asm volatile("cp.async.wait_group %0;" :: "n"(N) : "memory");
}
__device__ __forceinline__ void ldm_x4(uint32_t& r0, uint32_t& r1,
                                       uint32_t& r2, uint32_t& r3, uint32_t a) {
    asm volatile("ldmatrix.sync.aligned.m8n8.x4.shared.b16 {%0,%1,%2,%3}, [%4];"
                 : "=r"(r0), "=r"(r1), "=r"(r2), "=r"(r3) : "r"(a));
}
__device__ __forceinline__ void mma_f16(float* c, const uint32_t* a,
                                        const uint32_t* b) {
    asm volatile(
        "mma.sync.aligned.m16n8k16.row.col.f32.f16.f16.f32 "
        "{%0,%1,%2,%3}, {%4,%5,%6,%7}, {%8,%9}, {%0,%1,%2,%3};"
        : "+f"(c[0]), "+f"(c[1]), "+f"(c[2]), "+f"(c[3])
        : "r"(a[0]), "r"(a[1]), "r"(a[2]), "r"(a[3]), "r"(b[0]), "r"(b[1]));
}
__device__ __forceinline__ uint32_t packh(float a, float b) {
    __half2 h = __floats2half2_rn(a, b);
    return *reinterpret_cast<uint32_t*>(&h);
}

// ---------------------------------------------------------------------------
// fused fp32 -> fp16 convert of x, w_qkv (q rows pre-scaled 0.125), w_out
// ---------------------------------------------------------------------------
#define N4_X  (MR * DD / 4)
#define N4_WQ (QC * DD / 4)
#define N4_WO (DD * DD / 4)
__global__ __launch_bounds__(256) void conv_all(
    const float4* __restrict__ x, const float4* __restrict__ wq,
    const float4* __restrict__ wo,
    __half2* __restrict__ xh, __half2* __restrict__ wqh,
    __half2* __restrict__ woh)
{
    int i = blockIdx.x * blockDim.x + threadIdx.x;
    const float4* src;
    __half2* dst;
    float sc = 1.0f;
    if (i < N4_X)                { src = x;  dst = xh;  }
    else if (i < N4_X + N4_WQ) {
        i -= N4_X;  src = wq; dst = wqh;
        if (i < DD * DD / 4) sc = 0.125f;     // q rows: fold attn scale
    }
    else if (i < N4_X + N4_WQ + N4_WO) { i -= N4_X + N4_WQ; src = wo; dst = woh; }
    else return;
    float4 v = src[i];
    dst[2 * i]     = __floats2half2_rn(v.x * sc, v.y * sc);
    dst[2 * i + 1] = __floats2half2_rn(v.z * sc, v.w * sc);
}

// ---------------------------------------------------------------------------
// QKV GEMM with fused RoPE / V-transpose epilogue.
// C tile 128x128 = qkv[m0.., n0..]; n0<1024 -> Q (rope), <2048 -> K (rope),
// else V (transpose to Vt[nb][h][d][t]). 8 warps, BK=64, 2-stage.
// ---------------------------------------------------------------------------
__global__ __launch_bounds__(256) void gemm_qkv(
    const __half* __restrict__ A, const __half* __restrict__ B,
    __half* __restrict__ Q, __half* __restrict__ K, __half* __restrict__ Vt)
{
    extern __shared__ char sm[];
    const uint32_t smb = s2u(sm);

    const int tid  = threadIdx.x;
    const int lane = tid & 31;
    const int wid  = tid >> 5;
    const int wm   = wid & 1;
    const int wn   = wid >> 1;
    const int m0   = blockIdx.y * 128;
    const int n0   = blockIdx.x * 128;
    const int Kg   = DD;

    auto load_stage = [&](int st, int k0) {
        const uint32_t base = smb + st * GSTG;
#pragma unroll
        for (int j = 0; j < 4; j++) {
            const int idx = tid + j * 256;
            const int r = idx >> 3, c = idx & 7;
            const uint32_t d = base + (uint32_t)r * GROWB + c * 16;
            cp16(d,         A + (size_t)(m0 + r) * Kg + k0 + c * 8);
            cp16(d + GTILE, B + (size_t)(n0 + r) * Kg + k0 + c * 8);
        }
    };

    float acc[4][4][4];
#pragma unroll
    for (int i = 0; i < 4; i++)
#pragma unroll
        for (int j = 0; j < 4; j++)
#pragma unroll
            for (int k = 0; k < 4; k++) acc[i][j][k] = 0.f;

    load_stage(0, 0);
    cp_commit();

    const int S = Kg / BK;
    const int lrow = lane & 15, lhalf = lane >> 4;

    for (int s = 0; s < S; s++) {
        cp_wait<0>();
        __syncthreads();
        if (s + 1 < S) { load_stage((s + 1) & 1, (s + 1) * BK); cp_commit(); }

        const uint32_t stb = smb + (s & 1) * GSTG;
        const uint32_t aB = stb + (uint32_t)(wm * 64 + lrow) * GROWB + lhalf * 16;
        const uint32_t bB = stb + GTILE +
                            (uint32_t)(wn * 32 + lrow) * GROWB + lhalf * 16;
#pragma unroll
        for (int kd = 0; kd < 4; kd++) {
            const uint32_t ko = kd * 32;
            uint32_t a[4][4], bh[4][2];
#pragma unroll
            for (int mt = 0; mt < 4; mt++)
                ldm_x4(a[mt][0], a[mt][1], a[mt][2], a[mt][3],
                       aB + ko + mt * 16 * GROWB);
#pragma unroll
            for (int bt = 0; bt < 2; bt++) {
                uint32_t t0, t1, t2, t3;
                ldm_x4(t0, t1, t2, t3, bB + ko + bt * 16 * GROWB);
                bh[bt * 2][0] = t0;  bh[bt * 2][1] = t2;
                bh[bt * 2 + 1][0] = t1;  bh[bt * 2 + 1][1] = t3;
            }
#pragma unroll
            for (int mt = 0; mt < 4; mt++)
#pragma unroll
                for (int nt = 0; nt < 4; nt++)
                    mma_f16(acc[mt][nt], a[mt], bh[nt]);
        }
    }
    __syncthreads();   // all LDSM reads of last stage done before restaging

    // ---- stage C tile to smem fp16, pitch SP_E (conflict-free columns) ----
    const int erow = lane >> 2, ecol = (lane & 3) * 2;
#pragma unroll
    for (int mt = 0; mt < 4; mt++) {
        const int gr = wm * 64 + mt * 16 + erow;
#pragma unroll
        for (int nt = 0; nt < 4; nt++) {
            const int gc = wn * 32 + nt * 8 + ecol;
            *(uint32_t*)(sm + (size_t)gr * (SP_E * 2) + gc * 2) =
                packh(acc[mt][nt][0], acc[mt][nt][1]);
            *(uint32_t*)(sm + (size_t)(gr + 8) * (SP_E * 2) + gc * 2) =
                packh(acc[mt][nt][2], acc[mt][nt][3]);
        }
    }
    __syncthreads();

    const int nb = m0 / TT;
    const int tb = m0 % TT;

    if (n0 < 2 * DD) {
        // ---- RoPE path (Q or K) ----
        __half* dst = (n0 < DD) ? Q : K;
        const int h0 = (n0 & (DD - 1)) >> 6;     // first of 2 heads in tile
        const int px = tid & 31;                 // freq index 0..31
        const int rb = tid >> 5;                 // 0..7
        const float inv = exp2f(-(float)px * FREQ_C);
#pragma unroll 4
        for (int it = 0; it < 16; it++) {
            const int r = rb + it * 8;
            const int t = tb + r;
            float sn, cs;
            sincosf((float)t * inv, &sn, &cs);
            const char* row = sm + (size_t)r * (SP_E * 2);
#pragma unroll
            for (int hh = 0; hh < 2; hh++) {
                const float x1 = __half2float(
                    *(const __half*)(row + (hh * 64 + px) * 2));
                const float x2 = __half2float(
                    *(const __half*)(row + (hh * 64 + px + 32) * 2));
                const size_t base =
                    ((size_t)(nb * HH + h0 + hh) * TT + t) * HD;
                dst[base + px]      = __float2half(x1 * cs - x2 * sn);
                dst[base + px + 32] = __float2half(x2 * cs + x1 * sn);
            }
        }
    } else {
        // ---- V transpose path -> Vt[nb][h][d][t] ----
        const int h0 = (n0 - 2 * DD) >> 6;
        const int r  = tid & 127;                // t-local, coalesced dim
        const int dh = tid >> 7;                 // 0..1 (which head)
        const char* col0 = sm + (size_t)r * (SP_E * 2) + dh * 128;
#pragma unroll 8
        for (int dd = 0; dd < 64; dd++) {
            const __half v = *(const __half*)(col0 + dd * 2);
            Vt[((size_t)(nb * HH + h0 + dh) * HD + dd) * TT + tb + r] = v;
        }
    }
}

// ---------------------------------------------------------------------------
// generic HMMA GEMM (out-projection): fp32 out + bias
// ---------------------------------------------------------------------------
__global__ __launch_bounds__(256) void gemm_out(
    int Ng, int Kg,
    const __half* __restrict__ A, const __half* __restrict__ B,
    const float* __restrict__ bias, float* __restrict__ C)
{
    extern __shared__ char sm[];
    const uint32_t smb = s2u(sm);

    const int tid  = threadIdx.x;
    const int lane = tid & 31;
    const int wid  = tid >> 5;
    const int wm   = wid & 1;
    const int wn   = wid >> 1;
    const int m0   = blockIdx.y * 128;
    const int n0   = blockIdx.x * 128;

    auto load_stage = [&](int st, int k0) {
        const uint32_t base = smb + st * GSTG;
#pragma unroll
        for (int j = 0; j < 4; j++) {
            const int idx = tid + j * 256;
            const int r = idx >> 3, c = idx & 7;
            const uint32_t d = base + (uint32_t)r * GROWB + c * 16;
            cp16(d,         A + (size_t)(m0 + r) * Kg + k0 + c * 8);
            cp16(d + GTILE, B + (size_t)(n0 + r) * Kg + k0 + c * 8);
        }
    };

    float acc[4][4][4];
#pragma unroll
    for (int i = 0; i < 4; i++)
#pragma unroll
        for (int j = 0; j < 4; j++)
#pragma unroll
            for (int k = 0; k < 4; k++) acc[i][j][k] = 0.f;

    load_stage(0, 0);
    cp_commit();

    const int S = Kg / BK;
    const int lrow = lane & 15, lhalf = lane >> 4;

    for (int s = 0; s < S; s++) {
        cp_wait<0>();
        __syncthreads();
        if (s + 1 < S) { load_stage((s + 1) & 1, (s + 1) * BK); cp_commit(); }

        const uint32_t stb = smb + (s & 1) * GSTG;
        const uint32_t aB = stb + (uint32_t)(wm * 64 + lrow) * GROWB + lhalf * 16;
        const uint32_t bB = stb + GTILE +
                            (uint32_t)(wn * 32 + lrow) * GROWB + lhalf * 16;
#pragma unroll
        for (int kd = 0; kd < 4; kd++) {
            const uint32_t ko = kd * 32;
            uint32_t a[4][4], bh[4][2];
#pragma unroll
            for (int mt = 0; mt < 4; mt++)
                ldm_x4(a[mt][0], a[mt][1], a[mt][2], a[mt][3],
                       aB + ko + mt * 16 * GROWB);
#pragma unroll
            for (int bt = 0; bt < 2; bt++) {
                uint32_t t0, t1, t2, t3;
                ldm_x4(t0, t1, t2, t3, bB + ko + bt * 16 * GROWB);
                bh[bt * 2][0] = t0;  bh[bt * 2][1] = t2;
                bh[bt * 2 + 1][0] = t1;  bh[bt * 2 + 1][1] = t3;
            }
#pragma unroll
            for (int mt = 0; mt < 4; mt++)
#pragma unroll
                for (int nt = 0; nt < 4; nt++)
                    mma_f16(acc[mt][nt], a[mt], bh[nt]);
        }
    }

    const int erow = lane >> 2, ecol = (lane & 3) * 2;
#pragma unroll
    for (int mt = 0; mt < 4; mt++) {
        const int gr = m0 + wm * 64 + mt * 16 + erow;
#pragma unroll
        for (int nt = 0; nt < 4; nt++) {
            const int gc = n0 + wn * 32 + nt * 8 + ecol;
            const float b0 = bias[gc], b1 = bias[gc + 1];
            float2 v0 = {acc[mt][nt][0] + b0, acc[mt][nt][1] + b1};
            float2 v1 = {acc[mt][nt][2] + b0, acc[mt][nt][3] + b1};
            *(float2*)(C + (size_t)gr * Ng + gc)       = v0;
            *(float2*)(C + (size_t)(gr + 8) * Ng + gc) = v1;
        }
    }
}

// ---------------------------------------------------------------------------
// MMA flash attention, 1-pass fp16: 64-query tile, 4 warps x 16 rows,
// 3 key chunks of 128 (diagonal first), boundary-safe via clamped loads +
// uniform [lo,hi] column window masks. 3 CTAs/SM.
// ---------------------------------------------------------------------------
__global__ __launch_bounds__(128, 3) void attn_mma(
    const __half* __restrict__ Q, const __half* __restrict__ K,
    const __half* __restrict__ Vt, __half* __restrict__ oh)
{
    extern __shared__ char sm[];
    const uint32_t smb = s2u(sm);

    const int tid = threadIdx.x, lane = tid & 31, w = tid >> 5;   // w<4
    const int i0 = blockIdx.x * 64, h = blockIdx.y, nb = blockIdx.z;
    const size_t qkbase = (size_t)(nb * HH + h) * TT;
    const size_t vbase  = (size_t)(nb * HH + h) * HD;

    const int lrow = lane & 15, half = lane >> 4;
    const int g = lane >> 2, qc = lane & 3;
    const int rl0 = w * 16 + g, rl1 = rl0 + 8;     // local rows 0..63
    const int gr0 = i0 + rl0, gr1 = i0 + rl1;      // global query rows

    // stage Q tile (64 rows) into SM_K area, pull frags to registers
    for (int idx = tid; idx < 64 * 8; idx += 128) {
        const int r = idx >> 3, c = idx & 7;
        cp16(smb + SM_K + r * KP + c * 16,
             Q + (qkbase + i0 + r) * HD + c * 8);
    }
    cp_commit(); cp_wait<0>(); __syncthreads();

    uint32_t qf[4][4];
    {
        const uint32_t aB = smb + SM_K + (uint32_t)(w * 16 + lrow) * KP + half * 16;
#pragma unroll
        for (int kd = 0; kd < 4; kd++)
            ldm_x4(qf[kd][0], qf[kd][1], qf[kd][2], qf[kd][3], aB + kd * 32);
    }
    __syncthreads();

    float of[8][4];
#pragma unroll
    for (int i = 0; i < 8; i++)
#pragma unroll
        for (int j = 0; j < 4; j++) of[i][j] = 0.f;
    float m0 = -1e30f, m1 = -1e30f, l0 = 0.f, l1 = 0.f;

    for (int cc = 0; cc < 3; cc++) {
        const int cm = (cc == 0) ? 1 : (cc == 1) ? 0 : 2;   // diag, left, right
        const int j0 = i0 + (cm - 1) * 128;
        if (j0 + 128 <= 0 || j0 >= TT) continue;            // partial chunks stay

        // load K chunk (clamped rows) + V chunk (clamped t-cols)
        for (int idx = tid; idx < 128 * 8; idx += 128) {
            const int r = idx >> 3, c = idx & 7;
            int t = j0 + r;
            t = (t < 0) ? 0 : ((t >= TT) ? TT - 1 : t);
            cp16(smb + SM_K + r * KP + c * 16,
                 K + (qkbase + t) * HD + c * 8);
        }
        for (int idx = tid; idx < 64 * 16; idx += 128) {
            const int r = idx >> 4, c = idx & 15;
            int t = j0 + c * 8;
            t = (t < 0) ? 0 : ((t > TT - 8) ? TT - 8 : t);
            cp16(smb + SM_V + r * VP + c * 16,
                 Vt + (vbase + r) * TT + t);
        }
        cp_commit(); cp_wait<0>(); __syncthreads();

        // S = Q K^T (1-pass fp16)
        float sf[16][4];
#pragma unroll
        for (int i = 0; i < 16; i++)
#pragma unroll
            for (int j = 0; j < 4; j++) sf[i][j] = 0.f;

        const uint32_t bB = smb + SM_K + (uint32_t)lrow * KP + half * 16;
#pragma unroll
        for (int kd = 0; kd < 4; kd++) {
#pragma unroll
            for (int nt16 = 0; nt16 < 8; nt16++) {
                uint32_t t0, t1, t2, t3;
                ldm_x4(t0, t1, t2, t3, bB + nt16 * 16 * KP + kd * 32);
                uint32_t b0[2] = {t0, t2}, b1[2] = {t1, t3};
                mma_f16(sf[2 * nt16],     qf[kd], b0);
                mma_f16(sf[2 * nt16 + 1], qf[kd], b1);
            }
        }

        // uniform mask: local col valid iff lo<=col<=hi (band ∩ [0,TT))
        {
            int lo0 = gr0 - 127 - j0;  if (lo0 < -j0) lo0 = -j0;
            int hi0 = gr0 + 128 - j0;  if (hi0 > TT - 1 - j0) hi0 = TT - 1 - j0;
            int lo1 = gr1 - 127 - j0;  if (lo1 < -j0) lo1 = -j0;
            int hi1 = gr1 + 128 - j0;  if (hi1 > TT - 1 - j0) hi1 = TT - 1 - j0;
#pragma unroll
            for (int nt = 0; nt < 16; nt++) {
                const int c0 = nt * 8 + 2 * qc, c1 = c0 + 1;
                if (c0 < lo0 || c0 > hi0) sf[nt][0] = -1e30f;
                if (c1 < lo0 || c1 > hi0) sf[nt][1] = -1e30f;
                if (c0 < lo1 || c0 > hi1) sf[nt][2] = -1e30f;
                if (c1 < lo1 || c1 > hi1) sf[nt][3] = -1e30f;
            }
        }

        // online softmax
        float mx0 = -1e30f, mx1 = -1e30f;
#pragma unroll
        for (int nt = 0; nt < 16; nt++) {
            mx0 = fmaxf(mx0, fmaxf(sf[nt][0], sf[nt][1]));
            mx1 = fmaxf(mx1, fmaxf(sf[nt][2], sf[nt][3]));
        }
        mx0 = fmaxf(mx0, __shfl_xor_sync(0xffffffffu, mx0, 1));
        mx0 = fmaxf(mx0, __shfl_xor_sync(0xffffffffu, mx0, 2));
        mx1 = fmaxf(mx1, __shfl_xor_sync(0xffffffffu, mx1, 1));
        mx1 = fmaxf(mx1, __shfl_xor_sync(0xffffffffu, mx1, 2));
        const float mn0 = fmaxf(m0, mx0), mn1 = fmaxf(m1, mx1);
        const float a0 = __expf(m0 - mn0), a1 = __expf(m1 - mn1);
        m0 = mn0; m1 = mn1;
        float s0 = 0.f, s1 = 0.f;
#pragma unroll
        for (int nt = 0; nt < 16; nt++) {
            sf[nt][0] = __expf(sf[nt][0] - m0);
            sf[nt][1] = __expf(sf[nt][1] - m0);
            sf[nt][2] = __expf(sf[nt][2] - m1);
            sf[nt][3] = __expf(sf[nt][3] - m1);
            s0 += sf[nt][0] + sf[nt][1];
            s1 += sf[nt][2] + sf[nt][3];
        }
        s0 += __shfl_xor_sync(0xffffffffu, s0, 1);
        s0 += __shfl_xor_sync(0xffffffffu, s0, 2);
        s1 += __shfl_xor_sync(0xffffffffu, s1, 1);
        s1 += __shfl_xor_sync(0xffffffffu, s1, 2);
        l0 = l0 * a0 + s0;
        l1 = l1 * a1 + s1;
#pragma unroll
        for (int nt = 0; nt < 8; nt++) {
            of[nt][0] *= a0; of[nt][1] *= a0;
            of[nt][2] *= a1; of[nt][3] *= a1;
        }

        // O += P V (1-pass fp16)
        const uint32_t vB = smb + SM_V + (uint32_t)lrow * VP + half * 16;
#pragma unroll
        for (int kk = 0; kk < 8; kk++) {
            uint32_t ph[4];
            ph[0] = packh(sf[2 * kk][0],     sf[2 * kk][1]);
            ph[1] = packh(sf[2 * kk][2],     sf[2 * kk][3]);
            ph[2] = packh(sf[2 * kk + 1][0], sf[2 * kk + 1][1]);
            ph[3] = packh(sf[2 * kk + 1][2], sf[2 * kk + 1][3]);
#pragma unroll
            for (int nv = 0; nv < 4; nv++) {
                uint32_t t0, t1, t2, t3;
                ldm_x4(t0, t1, t2, t3, vB + nv * 16 * VP + kk * 32);
                uint32_t v0[2] = {t0, t2}, v1[2] = {t1, t3};
                mma_f16(of[2 * nv],     ph, v0);
                mma_f16(of[2 * nv + 1], ph, v1);
            }
        }
        __syncthreads();
    }

    // normalize, convert to fp16, store
    const float i0f = 1.0f / l0, i1f = 1.0f / l1;
#pragma unroll
    for (int nt = 0; nt < 8; nt++) {
        const int col = h * HD + nt * 8 + 2 * qc;
        *(uint32_t*)(oh + (size_t)(nb * TT + gr0) * DD + col) =
            packh(of[nt][0] * i0f, of[nt][1] * i0f);
        *(uint32_t*)(oh + (size_t)(nb * TT + gr1) * DD + col) =
            packh(of[nt][2] * i1f, of[nt][3] * i1f);
    }
}

// ---------------------------------------------------------------------------
extern "C" void kernel_launch(void* const* d_in, const int* in_sizes, int n_in,
                              void* d_out, int out_size)
{
    const float* x     = (const float*)d_in[0];
    const float* w_qkv = (const float*)d_in[1];
    const float* w_out = (const float*)d_in[2];
    const float* b_out = (const float*)d_in[3];
    float* out = (float*)d_out;

    __half *xh, *wqh, *woh, *ah, *q, *k, *vt;
    cudaGetSymbolAddress((void**)&xh,  g_xh);
    cudaGetSymbolAddress((void**)&wqh, g_wqh);
    cudaGetSymbolAddress((void**)&woh, g_woh);
    cudaGetSymbolAddress((void**)&ah,  g_ah);
    cudaGetSymbolAddress((void**)&q,   g_q);
    cudaGetSymbolAddress((void**)&k,   g_k);
    cudaGetSymbolAddress((void**)&vt,  g_vt);

    cudaFuncSetAttribute(gemm_qkv,
                         cudaFuncAttributeMaxDynamicSharedMemorySize, GEMM_SMEM);
    cudaFuncSetAttribute(gemm_out,
                         cudaFuncAttributeMaxDynamicSharedMemorySize, GEMM_SMEM);
    cudaFuncSetAttribute(attn_mma,
                         cudaFuncAttributeMaxDynamicSharedMemorySize, ATTN_SMEM);

    // 1) convert x, w_qkv (q rows x0.125), w_out to fp16 (one launch)
    {
        const int n4 = N4_X + N4_WQ + N4_WO;
        conv_all<<<(n4 + 255) / 256, 256>>>(
            (const float4*)x, (const float4*)w_qkv, (const float4*)w_out,
            (__half2*)xh, (__half2*)wqh, (__half2*)woh);
    }

    // 2) QKV projection with fused RoPE / V-transpose epilogue
    {
        dim3 grid(QC / 128, MR / 128);
        gemm_qkv<<<grid, 256, GEMM_SMEM>>>(xh, wqh, q, k, vt);
    }

    // 3) MMA flash attention (banded, 1-pass fp16, 64-q tiles) -> ah fp16
    {
        dim3 grid(TT / 64, HH, NB);
        attn_mma<<<grid, 128, ATTN_SMEM>>>(q, k, vt, ah);
    }

    // 4) output projection (fp16 HMMA) + bias -> fp32 out
    {
        dim3 grid(DD / 128, MR / 128);
        gemm_out<<<grid, 256, GEMM_SMEM>>>(DD, DD, ah, woh, b_out, out);
    }
}